// round 15
// baseline (speedup 1.0000x reference)
#include <cuda_runtime.h>

#define B_   256
#define T_   1000
#define H_   256
#define DIN  64
#define DOUT 64
#define NC_  10
#define R_   4
#define NPAIR 64                /* row-groups (pairs) */
#define NCTA  (NPAIR * 2)       /* 128 CTAs, 1 per SM */
#define NTHR 512
#define STEPS (T_ - 1)
#define LOGITS_OFF ((size_t)B_ * (size_t)T_ * (size_t)DOUT)
#define KP   128                /* k-pairs total (256 k / 2) */
#define KQT  32                 /* k-pairs per thread-quarter */

#define CAQ  12                 /* cached A k-pairs per quarter (stream 20 = 4x5) */
#define CBQ  11                 /* cached B k-pairs per quarter (stream 21 = 1+4x5) */
#define NSLAB_A (4 * CAQ)       /* 48 */
#define NSLAB_B (4 * CBQ)       /* 44 */
#define CACHE_BYTES ((NSLAB_A + NSLAB_B) * 128 * 16)   /* 184 KB dynamic smem */

// ---------------------------------------------------------------------------
// Device scratch (recomputed every call).
// g_WA[k2][j] = {Af[j][1+2k2], Ag[j][1+2k2], Af[j][2+2k2], Ag[j][2+2k2]}
// g_WB[k2][n] = {Wf2[n][2k2],  Wg2[n][2k2],  Wf2[n][2k2+1], Wg2[n][2k2+1]}
// ---------------------------------------------------------------------------
__device__ float4 g_WA[KP][H_];
__device__ float4 g_WB[KP][H_];
__device__ float2 g_a0 [H_];          // {Af[j][0], Ag[j][0]} (time row)
__device__ float2 g_cfg[H_];          // {Wf1@b_in+bf1, Wg1@bn+bg1}
__device__ float2 g_b2 [H_];          // {bf2, bg2}

// Exchange buffers + flags (zero-init; flags reset by their reader each launch).
__device__ float2   g_xh [NPAIR][2][R_][128];   // h halves   {hf,hg}
__device__ float2   g_xy01[NPAIR][2][128];      // {y0,y1} halves
__device__ float2   g_xy23[NPAIR][2][128];      // {y2,y3} halves
__device__ float    g_xz [NPAIR][2][R_][128];   // z_final halves
__device__ unsigned g_fh [NPAIR][2];
__device__ unsigned g_fy [NPAIR][2];
__device__ unsigned g_fz [NPAIR][2];

// ---------------------------------------------------------------------------
// Packed fp32x2 + sync helpers.
// ---------------------------------------------------------------------------
typedef unsigned long long u64;
__device__ __forceinline__ void ffma2(u64& acc, u64 a, u64 b) {
    asm("fma.rn.f32x2 %0, %1, %2, %0;" : "+l"(acc) : "l"(a), "l"(b));
}
__device__ __forceinline__ u64 fadd2(u64 a, u64 b) {
    u64 r; asm("add.rn.f32x2 %0, %1, %2;" : "=l"(r) : "l"(a), "l"(b)); return r;
}
__device__ __forceinline__ u64 pack2(float lo, float hi) {
    u64 r;
    asm("mov.b64 %0, {%1, %2};" : "=l"(r)
        : "r"(__float_as_uint(lo)), "r"(__float_as_uint(hi)));
    return r;
}
__device__ __forceinline__ float lo2(u64 v) {
    return __uint_as_float((unsigned)(v & 0xffffffffull));
}
__device__ __forceinline__ float hi2(u64 v) {
    return __uint_as_float((unsigned)(v >> 32));
}
__device__ __forceinline__ float lipswish(float x) {
    return 0.909f * x / (1.0f + __expf(-x));
}
__device__ __forceinline__ unsigned ld_acq(const unsigned* p) {
    unsigned v;
    asm volatile("ld.acquire.gpu.global.u32 %0, [%1];" : "=r"(v) : "l"(p) : "memory");
    return v;
}
__device__ __forceinline__ void red_rel(unsigned* p) {
    asm volatile("red.release.gpu.global.add.u32 [%0], 1;" :: "l"(p) : "memory");
}
__device__ __forceinline__ float2 ld_f2_strong(const float2* p) {
    float2 v;
    asm volatile("ld.acquire.gpu.global.v2.f32 {%0,%1}, [%2];"
                 : "=f"(v.x), "=f"(v.y) : "l"(p) : "memory");
    return v;
}
__device__ __forceinline__ float ld_f_strong(const float* p) {
    float v;
    asm volatile("ld.acquire.gpu.global.f32 %0, [%1];" : "=f"(v) : "l"(p) : "memory");
    return v;
}
__device__ __forceinline__ void spin_ge(const unsigned* p, unsigned target) {
    while (ld_acq(p) < target) { }
}

// ---------------------------------------------------------------------------
// Prep 1: fuse the linear pairs; emit k-pair layout.
// ---------------------------------------------------------------------------
__global__ __launch_bounds__(256) void sde_prep_fuse(
    const float* __restrict__ W_in, const float* __restrict__ b_in,
    const float* __restrict__ Wf1,  const float* __restrict__ bf1,
    const float* __restrict__ Wn,   const float* __restrict__ bn,
    const float* __restrict__ Wg1,  const float* __restrict__ bg1)
{
    __shared__ float cin[H_], cn[H_];
    const int j = threadIdx.x;
    const int k = blockIdx.x;                 // 0..257
    if (k < H_ + 1) { cin[j] = W_in[j * (H_ + 1) + k]; cn[j] = Wn[j * (H_ + 1) + k]; }
    else            { cin[j] = b_in[j];                cn[j]  = bn[j]; }
    __syncthreads();
    const float* wf1r = Wf1 + (size_t)j * H_;
    const float* wg1r = Wg1 + (size_t)j * H_;
    float af = 0.f, ag = 0.f;
#pragma unroll 8
    for (int m = 0; m < H_; m++) {
        af = fmaf(wf1r[m], cin[m], af);
        ag = fmaf(wg1r[m], cn[m],  ag);
    }
    if (k == 0) {
        g_a0[j] = make_float2(af, ag);
    } else if (k <= H_) {
        const int k2 = (k - 1) >> 1, pos = (k - 1) & 1;
        float* p = reinterpret_cast<float*>(&g_WA[k2][j]);
        p[2 * pos] = af; p[2 * pos + 1] = ag;
    } else {
        g_cfg[j] = make_float2(af + bf1[j], ag + bg1[j]);
    }
}

// ---------------------------------------------------------------------------
// Prep 2: transpose second-layer weights into k-pair layout.
// ---------------------------------------------------------------------------
__global__ __launch_bounds__(256) void sde_prep_w2(
    const float* __restrict__ Wf2, const float* __restrict__ bf2,
    const float* __restrict__ Wg2, const float* __restrict__ bg2)
{
    const int n = threadIdx.x;
    const int k = blockIdx.x;                 // 0..255
    const int k2 = k >> 1, pos = k & 1;
    float* p = reinterpret_cast<float*>(&g_WB[k2][n]);
    p[2 * pos]     = Wf2[(size_t)n * H_ + k];
    p[2 * pos + 1] = Wg2[(size_t)n * H_ + k];
    if (k == 0) g_b2[n] = make_float2(bf2[n], bg2[n]);
}

// one k-pair of {f,g}-packed MMA: acc_r += act_r[2k2]*w.x + act_r[2k2+1]*w.y
#define MM_STEP(ARR, K2, W) do {                                              \
    const ulonglong2 _v0 = *reinterpret_cast<const ulonglong2*>(&ARR[0][2*(K2)]); \
    const ulonglong2 _v1 = *reinterpret_cast<const ulonglong2*>(&ARR[1][2*(K2)]); \
    const ulonglong2 _v2 = *reinterpret_cast<const ulonglong2*>(&ARR[2][2*(K2)]); \
    const ulonglong2 _v3 = *reinterpret_cast<const ulonglong2*>(&ARR[3][2*(K2)]); \
    ffma2(ac0, _v0.x, (W).x); ffma2(ac0, _v0.y, (W).y);                       \
    ffma2(ac1, _v1.x, (W).x); ffma2(ac1, _v1.y, (W).y);                       \
    ffma2(ac2, _v2.x, (W).x); ffma2(ac2, _v2.y, (W).y);                       \
    ffma2(ac3, _v3.x, (W).x); ffma2(ac3, _v3.y, (W).y);                       \
} while (0)

// ---------------------------------------------------------------------------
// Main: 128 CTAs x 512 threads. Pair p = blockIdx>>1 owns rows 4p..4p+3;
// rank = blockIdx&1 owns output half j in [128*rank, 128*rank+128).
// Threads: jl = tid&127, kq = tid>>7. Per quarter: CAQ/CBQ cached k-pairs
// (smem-pinned) act as latency filler for the 20-21 streamed ones.
// ---------------------------------------------------------------------------
__global__ __launch_bounds__(NTHR, 1) void sde_main(
    const float* __restrict__ coeffs, const float* __restrict__ times,
    const int*   __restrict__ mask,   const float* __restrict__ noise,
    const float* __restrict__ W0,     const float* __restrict__ b0,
    const float* __restrict__ Wd,     const float* __restrict__ bd,
    const float* __restrict__ Wc,     const float* __restrict__ bc,
    float* __restrict__ out)
{
    extern __shared__ float4 s_w[];              // [NSLAB_A+NSLAB_B][128]

    __shared__ float2 s_y01[H_];        // {y_row0, y_row1}[k]   (pred)
    __shared__ float2 s_y23[H_];        // {y_row2, y_row3}[k]   (pred)
    __shared__ float2 s_yd [R_][H_];    // {y_r, y_r}[k]         (phase A)
    __shared__ float2 s_hfg[R_][H_];    // {hf_r, hg_r}[k]       (phase B)
    __shared__ u64    s_red[3][4][128]; // partials from kq 1..3
    __shared__ float2 s_part[8][DOUT];  // pred partials; aliases s_x0 at init
    __shared__ int    s_len[R_];

    float* s_zf = reinterpret_cast<float*>(s_hfg);    // [R_][H_] alias (end)
    float* s_x0 = reinterpret_cast<float*>(s_part);   // [R_][DIN] alias (init)

    const int tid   = threadIdx.x;
    const int pair  = blockIdx.x >> 1;
    const int rank  = blockIdx.x & 1;
    const int prank = rank ^ 1;
    const int row0  = pair * R_;
    const int jl    = tid & 127;
    const int j     = rank * 128 + jl;
    const int kq    = tid >> 7;             // 0..3

    // ---- init ----
    if (tid < R_) s_len[tid] = 0;
    if (tid < DIN) {
#pragma unroll
        for (int r = 0; r < R_; r++)
            s_x0[r * DIN + tid] = coeffs[(size_t)(row0 + r) * (size_t)(T_ - 1) * (4 * DIN) + tid];
    }
    // fill the weight cache (own j-half, quarter-interleaved slabs)
    for (int idx = tid; idx < NSLAB_A * 128; idx += NTHR) {
        const int s = idx >> 7, jj = idx & 127;
        const int q = s / CAQ, c = s % CAQ;
        s_w[(size_t)s * 128 + jj] = g_WA[q * KQT + c][rank * 128 + jj];
    }
    for (int idx = tid; idx < NSLAB_B * 128; idx += NTHR) {
        const int s = idx >> 7, jj = idx & 127;
        const int q = s / CBQ, c = s % CBQ;
        s_w[(size_t)(NSLAB_A + s) * 128 + jj] = g_WB[q * KQT + c][rank * 128 + jj];
    }
    __syncthreads();
    {
        int acc[R_] = {0, 0, 0, 0};
        for (int t = tid; t < T_; t += NTHR) {
#pragma unroll
            for (int r = 0; r < R_; r++) acc[r] += mask[(size_t)(row0 + r) * T_ + t];
        }
#pragma unroll
        for (int r = 0; r < R_; r++) atomicAdd(&s_len[r], acc[r]);
    }
    __syncthreads();
    int lastidx[R_];
#pragma unroll
    for (int r = 0; r < R_; r++) lastidx[r] = s_len[r] - 1;

    // ---- per-thread constants ----
    const float2 a0  = g_a0[j];
    const u64 p_a0  = pack2(a0.x, a0.y);    // {Af0, Ag0}
    const float2 ccf = g_cfg[j];
    const float2 cb2 = g_b2[j];
    const int pm = tid & 63;
    const int pq = tid >> 6;                // 0..7 (pred k-eighth)

    // Wd slice in registers (32 consecutive k for output pm).
    float wdr[32];
    {
        const float* p = Wd + (size_t)pm * H_ + pq * 32;
#pragma unroll
        for (int kk = 0; kk < 32; kk++) wdr[kk] = p[kk];
    }

    // ---- y0 = x0 @ W0^T + b0 : threads 0..255 compute ALL j ----
    if (tid < H_) {
        const int jj = tid;
        const float* w0r = W0 + (size_t)jj * DIN;
        const float  bb  = b0[jj];
        float a[R_];
#pragma unroll
        for (int r = 0; r < R_; r++) {
            float s = bb;
#pragma unroll 16
            for (int d = 0; d < DIN; d++) s = fmaf(s_x0[r * DIN + d], w0r[d], s);
            a[r] = s;
        }
        s_y01[jj] = make_float2(a[0], a[1]);
        s_y23[jj] = make_float2(a[2], a[3]);
#pragma unroll
        for (int r = 0; r < R_; r++) s_yd[r][jj] = make_float2(a[r], a[r]);
    }
    __syncthreads();

    // kq0 threads own the y-state for their j (all 4 rows).
    float y[R_] = {0.f, 0.f, 0.f, 0.f};
    float zfin[R_] = {0.f, 0.f, 0.f, 0.f};
    float t_cur = 0.f;
    if (kq == 0) {
        const float2 v01 = s_y01[j], v23 = s_y23[j];
        y[0] = v01.x; y[1] = v01.y; y[2] = v23.x; y[3] = v23.y;
#pragma unroll
        for (int r = 0; r < R_; r++) zfin[r] = y[r];    // covers lastidx == 0
        t_cur = __ldg(&times[0]);
    }

    // ---- pred accumulate (all 512 threads; rank picks its 2 rows) ----
    auto pred_acc = [&]() {
        const float2* ya = rank ? s_y23 : s_y01;
        u64 acc = 0ull;
        const int kbase = pq * 32;
#pragma unroll
        for (int g = 0; g < 16; g++) {
            const ulonglong2 v = *reinterpret_cast<const ulonglong2*>(&ya[kbase + 2 * g]);
            ffma2(acc, v.x, pack2(wdr[2 * g],     wdr[2 * g]));
            ffma2(acc, v.y, pack2(wdr[2 * g + 1], wdr[2 * g + 1]));
        }
        s_part[pq][pm] = make_float2(lo2(acc), hi2(acc));
    };
    // ---- pred gather + store (kq==1 threads) ----
    auto pred_gather = [&](int idx) {
        const int t  = tid & 127;
        const int m  = t & 63;
        const int rr = t >> 6;
        const int row = 2 * rank + rr;
        float v = __ldg(&bd[m]);
#pragma unroll
        for (int qq = 0; qq < 8; qq++) {
            const float2 pp = s_part[qq][m];
            v += rr ? pp.y : pp.x;
        }
        out[(size_t)(row0 + row) * T_ * DOUT + (size_t)idx * DOUT + m] = v;
    };

    const ulonglong2* gwa = reinterpret_cast<const ulonglong2*>(g_WA) + j;
    const ulonglong2* gwb = reinterpret_cast<const ulonglong2*>(g_WB) + j;
    const int kbA = kq * KQT;               // quarter base k-pair

    // ======================= main scan =======================
    for (int i = 0; ; i++) {
        // ---- top: pull peer y(i) half into smem (kq3) ----
        if (i > 0 && kq == 3) {
            spin_ge(&g_fy[pair][prank], 128u * (unsigned)i);
            const int pj = prank * 128 + jl;
            const float2 v01 = ld_f2_strong(&g_xy01[pair][prank][jl]);
            const float2 v23 = ld_f2_strong(&g_xy23[pair][prank][jl]);
            s_y01[pj] = v01; s_y23[pj] = v23;
            s_yd[0][pj] = make_float2(v01.x, v01.x);
            s_yd[1][pj] = make_float2(v01.y, v01.y);
            s_yd[2][pj] = make_float2(v23.x, v23.x);
            s_yd[3][pj] = make_float2(v23.y, v23.y);
        }
        __syncthreads();                                  // B1

        pred_acc();                                       // partials for index i
        if (i == STEPS) break;

        // prefetch time + noise (kq0)
        float tn = 0.f;
        float eps[R_];
        if (kq == 0) {
            tn = __ldg(&times[i + 1]);
            const float* np = noise + ((size_t)i * B_ + row0) * H_ + j;
#pragma unroll
            for (int r = 0; r < R_; r++) eps[r] = __ldg(np + (size_t)r * H_);
        }

        // ---------- phase A: {f,g}-pre = A @ [t; y] ----------
        u64 ac0, ac1, ac2, ac3;
        if (kq == 0) {
            u64 t0 = 0ull;
            ffma2(t0, pack2(t_cur, t_cur), p_a0);
            ac0 = ac1 = ac2 = ac3 = t0;
        } else { ac0 = ac1 = ac2 = ac3 = 0ull; }
        {
            const ulonglong2* wg = gwa + (size_t)(kbA + CAQ) * H_;
            ulonglong2 b0v[5], b1v[5];
#pragma unroll
            for (int p = 0; p < 5; p++) b0v[p] = wg[(size_t)p * H_];
#pragma unroll
            for (int p = 0; p < 5; p++) b1v[p] = wg[(size_t)(5 + p) * H_];
            // cached filler
            const float4* cs = &s_w[(size_t)(kq * CAQ) * 128 + jl];
#pragma unroll
            for (int c = 0; c < CAQ; c++) {
                const ulonglong2 w = *reinterpret_cast<const ulonglong2*>(cs + (size_t)c * 128);
                MM_STEP(s_yd, kbA + c, w);
            }
#pragma unroll
            for (int p = 0; p < 5; p++) {
                const ulonglong2 w = b0v[p]; b0v[p] = wg[(size_t)(10 + p) * H_];
                MM_STEP(s_yd, kbA + CAQ + p, w);
            }
#pragma unroll
            for (int p = 0; p < 5; p++) {
                const ulonglong2 w = b1v[p]; b1v[p] = wg[(size_t)(15 + p) * H_];
                MM_STEP(s_yd, kbA + CAQ + 5 + p, w);
            }
#pragma unroll
            for (int p = 0; p < 5; p++) MM_STEP(s_yd, kbA + CAQ + 10 + p, b0v[p]);
#pragma unroll
            for (int p = 0; p < 5; p++) MM_STEP(s_yd, kbA + CAQ + 15 + p, b1v[p]);
        }
        if (kq > 0) {
            s_red[kq - 1][0][jl] = ac0; s_red[kq - 1][1][jl] = ac1;
            s_red[kq - 1][2][jl] = ac2; s_red[kq - 1][3][jl] = ac3;
        }
        __syncthreads();                                  // B3
        if (kq == 0) {
#pragma unroll
            for (int q = 0; q < 3; q++) {
                ac0 = fadd2(ac0, s_red[q][0][jl]); ac1 = fadd2(ac1, s_red[q][1][jl]);
                ac2 = fadd2(ac2, s_red[q][2][jl]); ac3 = fadd2(ac3, s_red[q][3][jl]);
            }
            const float2 h0 = make_float2(lipswish(lo2(ac0) + ccf.x),
                                          lipswish(hi2(ac0) + ccf.y));
            const float2 h1 = make_float2(lipswish(lo2(ac1) + ccf.x),
                                          lipswish(hi2(ac1) + ccf.y));
            const float2 h2 = make_float2(lipswish(lo2(ac2) + ccf.x),
                                          lipswish(hi2(ac2) + ccf.y));
            const float2 h3 = make_float2(lipswish(lo2(ac3) + ccf.x),
                                          lipswish(hi2(ac3) + ccf.y));
            s_hfg[0][j] = h0; s_hfg[1][j] = h1; s_hfg[2][j] = h2; s_hfg[3][j] = h3;
            g_xh[pair][rank][0][jl] = h0; g_xh[pair][rank][1][jl] = h1;
            g_xh[pair][rank][2][jl] = h2; g_xh[pair][rank][3][jl] = h3;
            red_rel(&g_fh[pair][rank]);
        } else if (kq == 1) {
            pred_gather(i);                               // hidden in reduce shadow
        } else if (kq == 2) {
            spin_ge(&g_fh[pair][prank], 128u * (unsigned)(i + 1));
            const int pj = prank * 128 + jl;
#pragma unroll
            for (int r = 0; r < R_; r++)
                s_hfg[r][pj] = ld_f2_strong(&g_xh[pair][prank][r][jl]);
        }
        __syncthreads();                                  // B5

        // ---------- phase B: {f,g} = h @ W2 ----------
        ac0 = ac1 = ac2 = ac3 = 0ull;
        {
            const ulonglong2* wg = gwb + (size_t)(kbA + CBQ) * H_;
            const ulonglong2 bx = wg[0];                  // streamed extra kp
            const ulonglong2* wg5 = wg + H_;
            ulonglong2 b0v[5], b1v[5];
#pragma unroll
            for (int p = 0; p < 5; p++) b0v[p] = wg5[(size_t)p * H_];
#pragma unroll
            for (int p = 0; p < 5; p++) b1v[p] = wg5[(size_t)(5 + p) * H_];
            // cached filler
            const float4* cs = &s_w[(size_t)(NSLAB_A + kq * CBQ) * 128 + jl];
#pragma unroll
            for (int c = 0; c < CBQ; c++) {
                const ulonglong2 w = *reinterpret_cast<const ulonglong2*>(cs + (size_t)c * 128);
                MM_STEP(s_hfg, kbA + c, w);
            }
            MM_STEP(s_hfg, kbA + CBQ, bx);
#pragma unroll
            for (int p = 0; p < 5; p++) {
                const ulonglong2 w = b0v[p]; b0v[p] = wg5[(size_t)(10 + p) * H_];
                MM_STEP(s_hfg, kbA + CBQ + 1 + p, w);
            }
#pragma unroll
            for (int p = 0; p < 5; p++) {
                const ulonglong2 w = b1v[p]; b1v[p] = wg5[(size_t)(15 + p) * H_];
                MM_STEP(s_hfg, kbA + CBQ + 6 + p, w);
            }
#pragma unroll
            for (int p = 0; p < 5; p++) MM_STEP(s_hfg, kbA + CBQ + 11 + p, b0v[p]);
#pragma unroll
            for (int p = 0; p < 5; p++) MM_STEP(s_hfg, kbA + CBQ + 16 + p, b1v[p]);
        }
        if (kq > 0) {
            s_red[kq - 1][0][jl] = ac0; s_red[kq - 1][1][jl] = ac1;
            s_red[kq - 1][2][jl] = ac2; s_red[kq - 1][3][jl] = ac3;
        }
        __syncthreads();                                  // B6
        if (kq == 0) {
#pragma unroll
            for (int q = 0; q < 3; q++) {
                ac0 = fadd2(ac0, s_red[q][0][jl]); ac1 = fadd2(ac1, s_red[q][1][jl]);
                ac2 = fadd2(ac2, s_red[q][2][jl]); ac3 = fadd2(ac3, s_red[q][3][jl]);
            }
            const float dt = tn - t_cur;
            const float sd = sqrtf(dt);
            const u64 fg[R_] = {ac0, ac1, ac2, ac3};
#pragma unroll
            for (int r = 0; r < R_; r++) {
                const float f = lo2(fg[r]) + cb2.x;
                const float g = hi2(fg[r]) + cb2.y;
                y[r] = fmaf(f, dt, fmaf(g, sd * eps[r], y[r]));
                if (i + 1 == lastidx[r]) zfin[r] = y[r];
            }
            const float2 v01 = make_float2(y[0], y[1]);
            const float2 v23 = make_float2(y[2], y[3]);
            s_y01[j] = v01; s_y23[j] = v23;               // own half (local)
#pragma unroll
            for (int r = 0; r < R_; r++) s_yd[r][j] = make_float2(y[r], y[r]);
            g_xy01[pair][rank][jl] = v01;                 // to peer (L2)
            g_xy23[pair][rank][jl] = v23;
            red_rel(&g_fy[pair][rank]);
            t_cur = tn;
        }
        // no trailing barrier: B1 at next loop top publishes the y state
    }

    // ---- final pred gather (index = STEPS) + logits ----
    __syncthreads();
    if (kq == 1) pred_gather(STEPS);
    if (kq == 0) {
#pragma unroll
        for (int r = 0; r < R_; r++) {
            s_zf[r * H_ + j] = zfin[r];
            g_xz[pair][rank][r][jl] = zfin[r];
        }
        red_rel(&g_fz[pair][rank]);
    }
    if (kq == 2) {
        spin_ge(&g_fz[pair][prank], 128u);
        const int pj = prank * 128 + jl;
#pragma unroll
        for (int r = 0; r < R_; r++)
            s_zf[r * H_ + pj] = ld_f_strong(&g_xz[pair][prank][r][jl]);
    }
    __syncthreads();

    // logits for this rank's 2 rows
    if (tid < 2 * NC_) {
        const int rr = tid / NC_;
        const int c  = tid % NC_;
        const int row = 2 * rank + rr;
        const float* wcr = Wc + (size_t)c * H_;
        float a = bc[c];
#pragma unroll 8
        for (int k = 0; k < H_; k++) a = fmaf(s_zf[row * H_ + k], wcr[k], a);
        out[LOGITS_OFF + (size_t)(row0 + row) * NC_ + c] = a;
    }

    // ---- reset the flags this CTA consumed (peer-written) for next launch ----
    __syncthreads();
    if (tid == 0) {
        g_fh[pair][prank] = 0u;
        g_fy[pair][prank] = 0u;
        g_fz[pair][prank] = 0u;
    }
}

// ---------------------------------------------------------------------------
// Launch: prep kernels then the persistent paired scan. Stream-0 only,
// allocation-free, graph-capturable.
// ---------------------------------------------------------------------------
extern "C" void kernel_launch(void* const* d_in, const int* in_sizes, int n_in,
                              void* d_out, int out_size) {
    const float* coeffs = (const float*)d_in[0];
    const float* times  = (const float*)d_in[1];
    const int*   mask   = (const int*)  d_in[2];
    const float* noise  = (const float*)d_in[3];
    const float* W_in   = (const float*)d_in[4];
    const float* b_in   = (const float*)d_in[5];
    const float* Wf1    = (const float*)d_in[6];
    const float* bf1    = (const float*)d_in[7];
    const float* Wf2    = (const float*)d_in[8];
    const float* bf2    = (const float*)d_in[9];
    const float* Wn     = (const float*)d_in[10];
    const float* bn     = (const float*)d_in[11];
    const float* Wg1    = (const float*)d_in[12];
    const float* bg1    = (const float*)d_in[13];
    const float* Wg2    = (const float*)d_in[14];
    const float* bg2    = (const float*)d_in[15];
    const float* W0     = (const float*)d_in[16];
    const float* b0     = (const float*)d_in[17];
    const float* Wd     = (const float*)d_in[18];
    const float* bd     = (const float*)d_in[19];
    const float* Wc     = (const float*)d_in[20];
    const float* bc     = (const float*)d_in[21];
    float* out = (float*)d_out;

    cudaFuncSetAttribute(sde_main, cudaFuncAttributeMaxDynamicSharedMemorySize,
                         CACHE_BYTES);

    sde_prep_fuse<<<H_ + 2, 256>>>(W_in, b_in, Wf1, bf1, Wn, bn, Wg1, bg1);
    sde_prep_w2  <<<H_,     256>>>(Wf2, bf2, Wg2, bg2);
    sde_main     <<<NCTA, NTHR, CACHE_BYTES>>>(coeffs, times, mask, noise,
                                               W0, b0, Wd, bd, Wc, bc, out);
}

// round 16
// speedup vs baseline: 1.1907x; 1.1907x over previous
#include <cuda_runtime.h>

#define B_   256
#define T_   1000
#define H_   256
#define DIN  64
#define DOUT 64
#define NC_  10
#define R_   4
#define NPAIR 64                /* row-groups (pairs) */
#define NCTA  (NPAIR * 2)       /* 128 CTAs, 1 per SM */
#define NTHR 512
#define STEPS (T_ - 1)
#define LOGITS_OFF ((size_t)B_ * (size_t)T_ * (size_t)DOUT)
#define KP   128                /* k-pairs total (256 k / 2) */
#define KQT  32                 /* k-pairs per thread-quarter */

#define CAQ  12                 /* cached A k-pairs per quarter (stream 20 = 4x5) */
#define CBQ  11                 /* cached B k-pairs per quarter (stream 21 = 1+4x5) */
#define NSLAB_A (4 * CAQ)       /* 48 */
#define NSLAB_B (4 * CBQ)       /* 44 */
#define CACHE_BYTES ((NSLAB_A + NSLAB_B) * 128 * 16)   /* 184 KB dynamic smem */

// group barriers: quarters {0,1} = threads 0-255, quarters {2,3} = 256-511
#define BARQ01() asm volatile("bar.sync 1, 256;" ::: "memory")
#define BARQ23() asm volatile("bar.sync 2, 256;" ::: "memory")

// ---------------------------------------------------------------------------
// Device scratch (recomputed every call).
// g_WA[k2][j] = {Af[j][1+2k2], Ag[j][1+2k2], Af[j][2+2k2], Ag[j][2+2k2]}
// g_WB[k2][n] = {Wf2[n][2k2],  Wg2[n][2k2],  Wf2[n][2k2+1], Wg2[n][2k2+1]}
// ---------------------------------------------------------------------------
__device__ float4 g_WA[KP][H_];
__device__ float4 g_WB[KP][H_];
__device__ float2 g_a0 [H_];          // {Af[j][0], Ag[j][0]} (time row)
__device__ float2 g_cfg[H_];          // {Wf1@b_in+bf1, Wg1@bn+bg1}
__device__ float2 g_b2 [H_];          // {bf2, bg2}

// Exchange buffers + flags (zero-init; flags reset by their reader each launch).
__device__ float2   g_xh [NPAIR][2][R_][128];   // h halves   {hf,hg}
__device__ float2   g_xy01[NPAIR][2][128];      // {y0,y1} halves
__device__ float2   g_xy23[NPAIR][2][128];      // {y2,y3} halves
__device__ float    g_xz [NPAIR][2][R_][128];   // z_final halves
__device__ unsigned g_fh [NPAIR][2];
__device__ unsigned g_fy [NPAIR][2];
__device__ unsigned g_fz [NPAIR][2];

// ---------------------------------------------------------------------------
// Packed fp32x2 + sync helpers.
// ---------------------------------------------------------------------------
typedef unsigned long long u64;
__device__ __forceinline__ void ffma2(u64& acc, u64 a, u64 b) {
    asm("fma.rn.f32x2 %0, %1, %2, %0;" : "+l"(acc) : "l"(a), "l"(b));
}
__device__ __forceinline__ u64 fadd2(u64 a, u64 b) {
    u64 r; asm("add.rn.f32x2 %0, %1, %2;" : "=l"(r) : "l"(a), "l"(b)); return r;
}
__device__ __forceinline__ u64 pack2(float lo, float hi) {
    u64 r;
    asm("mov.b64 %0, {%1, %2};" : "=l"(r)
        : "r"(__float_as_uint(lo)), "r"(__float_as_uint(hi)));
    return r;
}
__device__ __forceinline__ float lo2(u64 v) {
    return __uint_as_float((unsigned)(v & 0xffffffffull));
}
__device__ __forceinline__ float hi2(u64 v) {
    return __uint_as_float((unsigned)(v >> 32));
}
__device__ __forceinline__ float lipswish(float x) {
    return 0.909f * x / (1.0f + __expf(-x));
}
__device__ __forceinline__ unsigned ld_acq(const unsigned* p) {
    unsigned v;
    asm volatile("ld.acquire.gpu.global.u32 %0, [%1];" : "=r"(v) : "l"(p) : "memory");
    return v;
}
__device__ __forceinline__ void red_rel(unsigned* p) {
    asm volatile("red.release.gpu.global.add.u32 [%0], 1;" :: "l"(p) : "memory");
}
__device__ __forceinline__ float2 ld_f2_strong(const float2* p) {
    float2 v;
    asm volatile("ld.acquire.gpu.global.v2.f32 {%0,%1}, [%2];"
                 : "=f"(v.x), "=f"(v.y) : "l"(p) : "memory");
    return v;
}
__device__ __forceinline__ float ld_f_strong(const float* p) {
    float v;
    asm volatile("ld.acquire.gpu.global.f32 %0, [%1];" : "=f"(v) : "l"(p) : "memory");
    return v;
}
__device__ __forceinline__ void spin_ge(const unsigned* p, unsigned target) {
    while (ld_acq(p) < target) { }
}

// tiny no-op kernels: shift ncu's -s/-c window so sde_main gets profiled
__global__ void sde_nop() {}

// ---------------------------------------------------------------------------
// Prep 1: fuse the linear pairs; emit k-pair layout.
// ---------------------------------------------------------------------------
__global__ __launch_bounds__(256) void sde_prep_fuse(
    const float* __restrict__ W_in, const float* __restrict__ b_in,
    const float* __restrict__ Wf1,  const float* __restrict__ bf1,
    const float* __restrict__ Wn,   const float* __restrict__ bn,
    const float* __restrict__ Wg1,  const float* __restrict__ bg1)
{
    __shared__ float cin[H_], cn[H_];
    const int j = threadIdx.x;
    const int k = blockIdx.x;                 // 0..257
    if (k < H_ + 1) { cin[j] = W_in[j * (H_ + 1) + k]; cn[j] = Wn[j * (H_ + 1) + k]; }
    else            { cin[j] = b_in[j];                cn[j]  = bn[j]; }
    __syncthreads();
    const float* wf1r = Wf1 + (size_t)j * H_;
    const float* wg1r = Wg1 + (size_t)j * H_;
    float af = 0.f, ag = 0.f;
#pragma unroll 8
    for (int m = 0; m < H_; m++) {
        af = fmaf(wf1r[m], cin[m], af);
        ag = fmaf(wg1r[m], cn[m],  ag);
    }
    if (k == 0) {
        g_a0[j] = make_float2(af, ag);
    } else if (k <= H_) {
        const int k2 = (k - 1) >> 1, pos = (k - 1) & 1;
        float* p = reinterpret_cast<float*>(&g_WA[k2][j]);
        p[2 * pos] = af; p[2 * pos + 1] = ag;
    } else {
        g_cfg[j] = make_float2(af + bf1[j], ag + bg1[j]);
    }
}

// ---------------------------------------------------------------------------
// Prep 2: transpose second-layer weights into k-pair layout.
// ---------------------------------------------------------------------------
__global__ __launch_bounds__(256) void sde_prep_w2(
    const float* __restrict__ Wf2, const float* __restrict__ bf2,
    const float* __restrict__ Wg2, const float* __restrict__ bg2)
{
    const int n = threadIdx.x;
    const int k = blockIdx.x;                 // 0..255
    const int k2 = k >> 1, pos = k & 1;
    float* p = reinterpret_cast<float*>(&g_WB[k2][n]);
    p[2 * pos]     = Wf2[(size_t)n * H_ + k];
    p[2 * pos + 1] = Wg2[(size_t)n * H_ + k];
    if (k == 0) g_b2[n] = make_float2(bf2[n], bg2[n]);
}

// one k-pair of {f,g}-packed MMA: acc_r += act_r[2k2]*w.x + act_r[2k2+1]*w.y
#define MM_STEP(ARR, K2, W) do {                                              \
    const ulonglong2 _v0 = *reinterpret_cast<const ulonglong2*>(&ARR[0][2*(K2)]); \
    const ulonglong2 _v1 = *reinterpret_cast<const ulonglong2*>(&ARR[1][2*(K2)]); \
    const ulonglong2 _v2 = *reinterpret_cast<const ulonglong2*>(&ARR[2][2*(K2)]); \
    const ulonglong2 _v3 = *reinterpret_cast<const ulonglong2*>(&ARR[3][2*(K2)]); \
    ffma2(ac0, _v0.x, (W).x); ffma2(ac0, _v0.y, (W).y);                       \
    ffma2(ac1, _v1.x, (W).x); ffma2(ac1, _v1.y, (W).y);                       \
    ffma2(ac2, _v2.x, (W).x); ffma2(ac2, _v2.y, (W).y);                       \
    ffma2(ac3, _v3.x, (W).x); ffma2(ac3, _v3.y, (W).y);                       \
} while (0)

// ---------------------------------------------------------------------------
// Main: 128 CTAs x 512 threads. Pair p = blockIdx>>1 owns rows 4p..4p+3;
// rank = blockIdx&1 owns output half j in [128*rank, 128*rank+128).
// Quarters 0-1 consume ONLY the CTA's own activation half; quarters 2-3 the
// peer half -> exchange latency overlaps quarters 0-1's compute.
// ---------------------------------------------------------------------------
__global__ __launch_bounds__(NTHR, 1) void sde_main(
    const float* __restrict__ coeffs, const float* __restrict__ times,
    const int*   __restrict__ mask,   const float* __restrict__ noise,
    const float* __restrict__ W0,     const float* __restrict__ b0,
    const float* __restrict__ Wd,     const float* __restrict__ bd,
    const float* __restrict__ Wc,     const float* __restrict__ bc,
    float* __restrict__ out)
{
    extern __shared__ float4 s_w[];              // [NSLAB_A+NSLAB_B][128]

    __shared__ float2 s_y01[H_];        // {y_row0, y_row1}[k]   (pred)
    __shared__ float2 s_y23[H_];        // {y_row2, y_row3}[k]   (pred)
    __shared__ float2 s_yd [R_][H_];    // {y_r, y_r}[k]         (phase A)
    __shared__ float2 s_hfg[R_][H_];    // {hf_r, hg_r}[k]       (phase B)
    __shared__ u64    s_red[3][4][128]; // partials from kq 1..3
    __shared__ float2 s_part[8][DOUT];  // pred partials; aliases s_x0 at init
    __shared__ int    s_len[R_];

    float* s_zf = reinterpret_cast<float*>(s_hfg);    // [R_][H_] alias (end)
    float* s_x0 = reinterpret_cast<float*>(s_part);   // [R_][DIN] alias (init)

    const int tid   = threadIdx.x;
    const int pair  = blockIdx.x >> 1;
    const int rank  = blockIdx.x & 1;
    const int prank = rank ^ 1;
    const int row0  = pair * R_;
    const int jl    = tid & 127;
    const int j     = rank * 128 + jl;
    const int kq    = tid >> 7;             // 0..3

    // quarter k-range: quarters 0-1 -> own activation half, 2-3 -> peer half
    const int qhalf = (kq < 2) ? rank : prank;
    const int kbA   = qhalf * 64 + (kq & 1) * KQT;   // base k-pair of this quarter

    // ---- init ----
    if (tid < R_) s_len[tid] = 0;
    if (tid < DIN) {
#pragma unroll
        for (int r = 0; r < R_; r++)
            s_x0[r * DIN + tid] = coeffs[(size_t)(row0 + r) * (size_t)(T_ - 1) * (4 * DIN) + tid];
    }
    // fill the weight cache (own j-half rows; k ranges follow the quarter map)
    for (int idx = tid; idx < NSLAB_A * 128; idx += NTHR) {
        const int s = idx >> 7, jj = idx & 127;
        const int q = s / CAQ, c = s % CAQ;
        const int qh = (q < 2) ? rank : prank;
        const int kb = qh * 64 + (q & 1) * KQT;
        s_w[(size_t)s * 128 + jj] = g_WA[kb + c][rank * 128 + jj];
    }
    for (int idx = tid; idx < NSLAB_B * 128; idx += NTHR) {
        const int s = idx >> 7, jj = idx & 127;
        const int q = s / CBQ, c = s % CBQ;
        const int qh = (q < 2) ? rank : prank;
        const int kb = qh * 64 + (q & 1) * KQT;
        s_w[(size_t)(NSLAB_A + s) * 128 + jj] = g_WB[kb + c][rank * 128 + jj];
    }
    __syncthreads();
    {
        int acc[R_] = {0, 0, 0, 0};
        for (int t = tid; t < T_; t += NTHR) {
#pragma unroll
            for (int r = 0; r < R_; r++) acc[r] += mask[(size_t)(row0 + r) * T_ + t];
        }
#pragma unroll
        for (int r = 0; r < R_; r++) atomicAdd(&s_len[r], acc[r]);
    }
    __syncthreads();
    int lastidx[R_];
#pragma unroll
    for (int r = 0; r < R_; r++) lastidx[r] = s_len[r] - 1;

    // ---- per-thread constants ----
    const float2 a0  = g_a0[j];
    const u64 p_a0  = pack2(a0.x, a0.y);    // {Af0, Ag0}
    const float2 ccf = g_cfg[j];
    const float2 cb2 = g_b2[j];
    const int pm = tid & 63;
    const int pq = tid >> 6;                // 0..7
    // pred k-eighth, rank-rotated so group {0,1} touches own half only
    const int pkbase = (((pq + rank * 4) & 7) * 32);

    // Wd slice in registers (32 consecutive k for output pm).
    float wdr[32];
    {
        const float* p = Wd + (size_t)pm * H_ + pkbase;
#pragma unroll
        for (int kk = 0; kk < 32; kk++) wdr[kk] = p[kk];
    }

    // ---- y0 = x0 @ W0^T + b0 : threads 0..255 compute ALL j ----
    if (tid < H_) {
        const int jj = tid;
        const float* w0r = W0 + (size_t)jj * DIN;
        const float  bb  = b0[jj];
        float a[R_];
#pragma unroll
        for (int r = 0; r < R_; r++) {
            float s = bb;
#pragma unroll 16
            for (int d = 0; d < DIN; d++) s = fmaf(s_x0[r * DIN + d], w0r[d], s);
            a[r] = s;
        }
        s_y01[jj] = make_float2(a[0], a[1]);
        s_y23[jj] = make_float2(a[2], a[3]);
#pragma unroll
        for (int r = 0; r < R_; r++) s_yd[r][jj] = make_float2(a[r], a[r]);
    }
    __syncthreads();

    // kq0 threads own the y-state for their j (all 4 rows).
    float y[R_] = {0.f, 0.f, 0.f, 0.f};
    float zfin[R_] = {0.f, 0.f, 0.f, 0.f};
    float t_cur = 0.f;
    if (kq == 0) {
        const float2 v01 = s_y01[j], v23 = s_y23[j];
        y[0] = v01.x; y[1] = v01.y; y[2] = v23.x; y[3] = v23.y;
#pragma unroll
        for (int r = 0; r < R_; r++) zfin[r] = y[r];    // covers lastidx == 0
        t_cur = __ldg(&times[0]);
    }

    // ---- pred accumulate (rank picks its 2 rows; k-eighth = pkbase) ----
    auto pred_acc = [&]() {
        const float2* ya = rank ? s_y23 : s_y01;
        u64 acc = 0ull;
#pragma unroll
        for (int g = 0; g < 16; g++) {
            const ulonglong2 v = *reinterpret_cast<const ulonglong2*>(&ya[pkbase + 2 * g]);
            ffma2(acc, v.x, pack2(wdr[2 * g],     wdr[2 * g]));
            ffma2(acc, v.y, pack2(wdr[2 * g + 1], wdr[2 * g + 1]));
        }
        s_part[pq][pm] = make_float2(lo2(acc), hi2(acc));
    };
    // ---- pred gather + store (kq==1 threads) ----
    auto pred_gather = [&](int idx) {
        const int t  = tid & 127;
        const int m  = t & 63;
        const int rr = t >> 6;
        const int row = 2 * rank + rr;
        float v = __ldg(&bd[m]);
#pragma unroll
        for (int qq = 0; qq < 8; qq++) {
            const float2 pp = s_part[qq][m];
            v += rr ? pp.y : pp.x;
        }
        out[(size_t)(row0 + row) * T_ * DOUT + (size_t)idx * DOUT + m] = v;
    };

    const ulonglong2* gwa = reinterpret_cast<const ulonglong2*>(g_WA) + j;
    const ulonglong2* gwb = reinterpret_cast<const ulonglong2*>(g_WB) + j;

    // ======================= main scan =======================
    for (int i = 0; ; i++) {
        // group-split step entry: own-half group proceeds on local state;
        // peer-half group absorbs the exchange latency.
        if (tid < 256) {
            BARQ01();                                 // kq0's y-writes -> kq1
        } else {
            if (i > 0 && kq == 3) {
                spin_ge(&g_fy[pair][prank], 128u * (unsigned)i);
                const int pj = prank * 128 + jl;
                const float2 v01 = ld_f2_strong(&g_xy01[pair][prank][jl]);
                const float2 v23 = ld_f2_strong(&g_xy23[pair][prank][jl]);
                s_y01[pj] = v01; s_y23[pj] = v23;
                s_yd[0][pj] = make_float2(v01.x, v01.x);
                s_yd[1][pj] = make_float2(v01.y, v01.y);
                s_yd[2][pj] = make_float2(v23.x, v23.x);
                s_yd[3][pj] = make_float2(v23.y, v23.y);
            }
            BARQ23();                                 // peer y visible to kq2
        }

        pred_acc();                                   // partials for index i
        if (i == STEPS) break;

        // prefetch time + noise (kq0)
        float tn = 0.f;
        float eps[R_];
        if (kq == 0) {
            tn = __ldg(&times[i + 1]);
            const float* np = noise + ((size_t)i * B_ + row0) * H_ + j;
#pragma unroll
            for (int r = 0; r < R_; r++) eps[r] = __ldg(np + (size_t)r * H_);
        }

        // ---------- phase A: {f,g}-pre = A @ [t; y] ----------
        u64 ac0, ac1, ac2, ac3;
        if (kq == 0) {
            u64 t0 = 0ull;
            ffma2(t0, pack2(t_cur, t_cur), p_a0);
            ac0 = ac1 = ac2 = ac3 = t0;
        } else { ac0 = ac1 = ac2 = ac3 = 0ull; }
        {
            const ulonglong2* wg = gwa + (size_t)(kbA + CAQ) * H_;
            ulonglong2 b0v[5], b1v[5];
#pragma unroll
            for (int p = 0; p < 5; p++) b0v[p] = wg[(size_t)p * H_];
#pragma unroll
            for (int p = 0; p < 5; p++) b1v[p] = wg[(size_t)(5 + p) * H_];
            const float4* cs = &s_w[(size_t)(kq * CAQ) * 128 + jl];
#pragma unroll
            for (int c = 0; c < CAQ; c++) {
                const ulonglong2 w = *reinterpret_cast<const ulonglong2*>(cs + (size_t)c * 128);
                MM_STEP(s_yd, kbA + c, w);
            }
#pragma unroll
            for (int p = 0; p < 5; p++) {
                const ulonglong2 w = b0v[p]; b0v[p] = wg[(size_t)(10 + p) * H_];
                MM_STEP(s_yd, kbA + CAQ + p, w);
            }
#pragma unroll
            for (int p = 0; p < 5; p++) {
                const ulonglong2 w = b1v[p]; b1v[p] = wg[(size_t)(15 + p) * H_];
                MM_STEP(s_yd, kbA + CAQ + 5 + p, w);
            }
#pragma unroll
            for (int p = 0; p < 5; p++) MM_STEP(s_yd, kbA + CAQ + 10 + p, b0v[p]);
#pragma unroll
            for (int p = 0; p < 5; p++) MM_STEP(s_yd, kbA + CAQ + 15 + p, b1v[p]);
        }
        if (kq > 0) {
            s_red[kq - 1][0][jl] = ac0; s_red[kq - 1][1][jl] = ac1;
            s_red[kq - 1][2][jl] = ac2; s_red[kq - 1][3][jl] = ac3;
        }
        __syncthreads();                              // B3 (full: reduce)
        if (kq == 0) {
#pragma unroll
            for (int q = 0; q < 3; q++) {
                ac0 = fadd2(ac0, s_red[q][0][jl]); ac1 = fadd2(ac1, s_red[q][1][jl]);
                ac2 = fadd2(ac2, s_red[q][2][jl]); ac3 = fadd2(ac3, s_red[q][3][jl]);
            }
            const float2 h0 = make_float2(lipswish(lo2(ac0) + ccf.x),
                                          lipswish(hi2(ac0) + ccf.y));
            const float2 h1 = make_float2(lipswish(lo2(ac1) + ccf.x),
                                          lipswish(hi2(ac1) + ccf.y));
            const float2 h2 = make_float2(lipswish(lo2(ac2) + ccf.x),
                                          lipswish(hi2(ac2) + ccf.y));
            const float2 h3 = make_float2(lipswish(lo2(ac3) + ccf.x),
                                          lipswish(hi2(ac3) + ccf.y));
            s_hfg[0][j] = h0; s_hfg[1][j] = h1; s_hfg[2][j] = h2; s_hfg[3][j] = h3;
            g_xh[pair][rank][0][jl] = h0; g_xh[pair][rank][1][jl] = h1;
            g_xh[pair][rank][2][jl] = h2; g_xh[pair][rank][3][jl] = h3;
            red_rel(&g_fh[pair][rank]);
        } else if (kq == 1) {
            pred_gather(i);                           // hidden in reduce shadow
        } else {
            spin_ge(&g_fh[pair][prank], 128u * (unsigned)(i + 1));
            const int pj = prank * 128 + jl;
            if (kq == 2) {
                s_hfg[0][pj] = ld_f2_strong(&g_xh[pair][prank][0][jl]);
                s_hfg[1][pj] = ld_f2_strong(&g_xh[pair][prank][1][jl]);
            } else {
                s_hfg[2][pj] = ld_f2_strong(&g_xh[pair][prank][2][jl]);
                s_hfg[3][pj] = ld_f2_strong(&g_xh[pair][prank][3][jl]);
            }
        }
        if (tid < 256) BARQ01(); else BARQ23();       // h halves visible per group

        // ---------- phase B: {f,g} = h @ W2 ----------
        ac0 = ac1 = ac2 = ac3 = 0ull;
        {
            const ulonglong2* wg = gwb + (size_t)(kbA + CBQ) * H_;
            const ulonglong2 bx = wg[0];              // streamed extra kp
            const ulonglong2* wg5 = wg + H_;
            ulonglong2 b0v[5], b1v[5];
#pragma unroll
            for (int p = 0; p < 5; p++) b0v[p] = wg5[(size_t)p * H_];
#pragma unroll
            for (int p = 0; p < 5; p++) b1v[p] = wg5[(size_t)(5 + p) * H_];
            const float4* cs = &s_w[(size_t)(NSLAB_A + kq * CBQ) * 128 + jl];
#pragma unroll
            for (int c = 0; c < CBQ; c++) {
                const ulonglong2 w = *reinterpret_cast<const ulonglong2*>(cs + (size_t)c * 128);
                MM_STEP(s_hfg, kbA + c, w);
            }
            MM_STEP(s_hfg, kbA + CBQ, bx);
#pragma unroll
            for (int p = 0; p < 5; p++) {
                const ulonglong2 w = b0v[p]; b0v[p] = wg5[(size_t)(10 + p) * H_];
                MM_STEP(s_hfg, kbA + CBQ + 1 + p, w);
            }
#pragma unroll
            for (int p = 0; p < 5; p++) {
                const ulonglong2 w = b1v[p]; b1v[p] = wg5[(size_t)(15 + p) * H_];
                MM_STEP(s_hfg, kbA + CBQ + 6 + p, w);
            }
#pragma unroll
            for (int p = 0; p < 5; p++) MM_STEP(s_hfg, kbA + CBQ + 11 + p, b0v[p]);
#pragma unroll
            for (int p = 0; p < 5; p++) MM_STEP(s_hfg, kbA + CBQ + 16 + p, b1v[p]);
        }
        if (kq > 0) {
            s_red[kq - 1][0][jl] = ac0; s_red[kq - 1][1][jl] = ac1;
            s_red[kq - 1][2][jl] = ac2; s_red[kq - 1][3][jl] = ac3;
        }
        __syncthreads();                              // B6 (full: reduce)
        if (kq == 0) {
#pragma unroll
            for (int q = 0; q < 3; q++) {
                ac0 = fadd2(ac0, s_red[q][0][jl]); ac1 = fadd2(ac1, s_red[q][1][jl]);
                ac2 = fadd2(ac2, s_red[q][2][jl]); ac3 = fadd2(ac3, s_red[q][3][jl]);
            }
            const float dt = tn - t_cur;
            const float sd = sqrtf(dt);
            const u64 fg[R_] = {ac0, ac1, ac2, ac3};
#pragma unroll
            for (int r = 0; r < R_; r++) {
                const float f = lo2(fg[r]) + cb2.x;
                const float g = hi2(fg[r]) + cb2.y;
                y[r] = fmaf(f, dt, fmaf(g, sd * eps[r], y[r]));
                if (i + 1 == lastidx[r]) zfin[r] = y[r];
            }
            const float2 v01 = make_float2(y[0], y[1]);
            const float2 v23 = make_float2(y[2], y[3]);
            s_y01[j] = v01; s_y23[j] = v23;           // own half (local)
#pragma unroll
            for (int r = 0; r < R_; r++) s_yd[r][j] = make_float2(y[r], y[r]);
            g_xy01[pair][rank][jl] = v01;             // to peer (L2)
            g_xy23[pair][rank][jl] = v23;
            red_rel(&g_fy[pair][rank]);
            t_cur = tn;
        }
        // next loop-top group barriers publish the state
    }

    // ---- final pred gather (index = STEPS) + logits ----
    __syncthreads();
    if (kq == 1) pred_gather(STEPS);
    if (kq == 0) {
#pragma unroll
        for (int r = 0; r < R_; r++) {
            s_zf[r * H_ + j] = zfin[r];
            g_xz[pair][rank][r][jl] = zfin[r];
        }
        red_rel(&g_fz[pair][rank]);
    }
    if (kq == 2) {
        spin_ge(&g_fz[pair][prank], 128u);
        const int pj = prank * 128 + jl;
#pragma unroll
        for (int r = 0; r < R_; r++)
            s_zf[r * H_ + pj] = ld_f_strong(&g_xz[pair][prank][r][jl]);
    }
    __syncthreads();

    // logits for this rank's 2 rows
    if (tid < 2 * NC_) {
        const int rr = tid / NC_;
        const int c  = tid % NC_;
        const int row = 2 * rank + rr;
        const float* wcr = Wc + (size_t)c * H_;
        float a = bc[c];
#pragma unroll 8
        for (int k = 0; k < H_; k++) a = fmaf(s_zf[row * H_ + k], wcr[k], a);
        out[LOGITS_OFF + (size_t)(row0 + row) * NC_ + c] = a;
    }

    // ---- reset the flags this CTA consumed (peer-written) for next launch ----
    __syncthreads();
    if (tid == 0) {
        g_fh[pair][prank] = 0u;
        g_fy[pair][prank] = 0u;
        g_fz[pair][prank] = 0u;
    }
}

// ---------------------------------------------------------------------------
// Launch: prep kernels, 3 alignment no-ops (ncu -s 5 -> sde_main), then the
// persistent paired scan. Stream-0 only, allocation-free, graph-capturable.
// ---------------------------------------------------------------------------
extern "C" void kernel_launch(void* const* d_in, const int* in_sizes, int n_in,
                              void* d_out, int out_size) {
    const float* coeffs = (const float*)d_in[0];
    const float* times  = (const float*)d_in[1];
    const int*   mask   = (const int*)  d_in[2];
    const float* noise  = (const float*)d_in[3];
    const float* W_in   = (const float*)d_in[4];
    const float* b_in   = (const float*)d_in[5];
    const float* Wf1    = (const float*)d_in[6];
    const float* bf1    = (const float*)d_in[7];
    const float* Wf2    = (const float*)d_in[8];
    const float* bf2    = (const float*)d_in[9];
    const float* Wn     = (const float*)d_in[10];
    const float* bn     = (const float*)d_in[11];
    const float* Wg1    = (const float*)d_in[12];
    const float* bg1    = (const float*)d_in[13];
    const float* Wg2    = (const float*)d_in[14];
    const float* bg2    = (const float*)d_in[15];
    const float* W0     = (const float*)d_in[16];
    const float* b0     = (const float*)d_in[17];
    const float* Wd     = (const float*)d_in[18];
    const float* bd     = (const float*)d_in[19];
    const float* Wc     = (const float*)d_in[20];
    const float* bc     = (const float*)d_in[21];
    float* out = (float*)d_out;

    cudaFuncSetAttribute(sde_main, cudaFuncAttributeMaxDynamicSharedMemorySize,
                         CACHE_BYTES);

    sde_prep_fuse<<<H_ + 2, 256>>>(W_in, b_in, Wf1, bf1, Wn, bn, Wg1, bg1);
    sde_prep_w2  <<<H_,     256>>>(Wf2, bf2, Wg2, bg2);
    sde_nop<<<1, 32>>>();
    sde_nop<<<1, 32>>>();
    sde_nop<<<1, 32>>>();
    sde_main     <<<NCTA, NTHR, CACHE_BYTES>>>(coeffs, times, mask, noise,
                                               W0, b0, Wd, bd, Wc, bc, out);
}